// round 6
// baseline (speedup 1.0000x reference)
#include <cuda_runtime.h>

// GaussianRP: x (8,16,32,1024) f32, log_sigma scalar f32
// out (8,16,1024,1024) f32:
//   rp[b,c,t,s] = exp(-max(|x_t|^2+|x_s|^2-2<x_t,x_s>, 0) / (2 sigma^2))
//
// Round 5: occupancy-fixed packed-fp32 kernel. 128x128 tile, 512 threads
// (32 cols x 16 row-groups), 8x4 microtile per thread held as 8x2 f32x2
// accumulators (32 regs). A-side smem duplicated so warp-uniform (broadcast)
// 16B LDS yields ready {a,a} packed operands; B pairs are contiguous u64s.
// Inner loop: 5 LDS.128 + 16 FFMA2 per k, nothing else. Symmetric tile-pair
// scheme (36 of 64 pairs); transposed store writes 32B/lane (full sectors).

#define NB   8
#define NC   16
#define NDIM 32
#define NT   1024
#define NBC  (NB * NC)

#define TILE  128
#define NTILE (NT / TILE)                  // 8
#define NPAIR (NTILE * (NTILE + 1) / 2)    // 36

typedef unsigned long long u64;

__device__ float g_sqnorm[NBC * NT];
__device__ float g_scale;   // 1/(2 sigma^2)

__device__ __forceinline__ float2 upk2(u64 v) {
    float2 f;
    asm("mov.b64 {%0, %1}, %2;" : "=f"(f.x), "=f"(f.y) : "l"(v));
    return f;
}
__device__ __forceinline__ u64 fma2(u64 a, u64 b, u64 c) {
    u64 d;
    asm("fma.rn.f32x2 %0, %1, %2, %3;" : "=l"(d) : "l"(a), "l"(b), "l"(c));
    return d;
}

__global__ __launch_bounds__(256)
void norms_kernel(const float* __restrict__ x,
                  const float* __restrict__ log_sigma) {
    int idx = blockIdx.x * blockDim.x + threadIdx.x;   // bc*NT + t
    if (idx == 0) g_scale = 0.5f * __expf(-2.f * log_sigma[0]);
    if (idx >= NBC * NT) return;
    int bc = idx >> 10;
    int t  = idx & (NT - 1);
    const float* p = x + (size_t)bc * NDIM * NT + t;
    float s = 0.f;
#pragma unroll
    for (int d = 0; d < NDIM; ++d) {
        float v = p[d * NT];
        s = fmaf(v, v, s);
    }
    g_sqnorm[idx] = s;
}

__global__ __launch_bounds__(512)
void gaussian_rp_kernel(const float* __restrict__ x,
                        float* __restrict__ out) {
    // A tile duplicated: At2[k][2*i] = At2[k][2*i+1] = x[k][t0+i]   (32 KB)
    // B tile plain:      As[k][j]    = x[k][s0+j]                    (16 KB)
    __shared__ __align__(16) float At2[NDIM][2 * TILE];
    __shared__ __align__(16) float As [NDIM][TILE];

    const int bc = blockIdx.x;
    const int p  = blockIdx.y;         // 0..NPAIR-1

    // triangular pair decode: p = ss*(ss+1)/2 + ts, ts <= ss
    int ss = 0;
#pragma unroll
    for (int c = 1; c < NTILE; ++c)
        ss += (p >= c * (c + 1) / 2) ? 1 : 0;
    const int ts = p - ss * (ss + 1) / 2;

    const int t0 = ts * TILE;
    const int s0 = ss * TILE;

    const int tx  = threadIdx.x;       // 0..31  (col group: 4 cols)
    const int ty  = threadIdx.y;       // 0..15  (row group: 8 rows)
    const int tid = ty * 32 + tx;      // 0..511

    // ---- load tiles: 32 rows x 128 cols each = 1024 float4 per side ----
    const float* xb = x + (size_t)bc * NDIM * NT;
#pragma unroll
    for (int r = 0; r < 2; ++r) {
        int lin = tid + 512 * r;       // 0..1023
        int d   = lin >> 5;            // k row
        int v   = lin & 31;            // float4 index within row
        float4 a = *(const float4*)(xb + d * NT + t0 + v * 4);
        float4 b = *(const float4*)(xb + d * NT + s0 + v * 4);
        *(float4*)&At2[d][v * 8]     = make_float4(a.x, a.x, a.y, a.y);
        *(float4*)&At2[d][v * 8 + 4] = make_float4(a.z, a.z, a.w, a.w);
        *(float4*)&As[d][v * 4] = b;
    }
    __syncthreads();

    // ---- 8x4 microtile as 8x2 packed accumulators ----
    // rows: t0 + 8*ty + i (i=0..7); cols: s0 + 4*tx + {0..3}
    u64 acc[8][2];
#pragma unroll
    for (int i = 0; i < 8; ++i) { acc[i][0] = 0ull; acc[i][1] = 0ull; }

#pragma unroll
    for (int k = 0; k < NDIM; ++k) {
        // duplicated A, warp-uniform address -> broadcast LDS.128 x4
        ulonglong2 a01 = *(const ulonglong2*)&At2[k][16 * ty];
        ulonglong2 a23 = *(const ulonglong2*)&At2[k][16 * ty + 4];
        ulonglong2 a45 = *(const ulonglong2*)&At2[k][16 * ty + 8];
        ulonglong2 a67 = *(const ulonglong2*)&At2[k][16 * ty + 12];
        // plain B: two contiguous packed pairs per thread
        ulonglong2 b01 = *(const ulonglong2*)&As[k][4 * tx];

        u64 aa[8] = { a01.x, a01.y, a23.x, a23.y,
                      a45.x, a45.y, a67.x, a67.y };
#pragma unroll
        for (int i = 0; i < 8; ++i) {
            acc[i][0] = fma2(aa[i], b01.x, acc[i][0]);
            acc[i][1] = fma2(aa[i], b01.y, acc[i][1]);
        }
    }

    // ---- epilogue: d2 -> exp ----
    const float scale  = g_scale;
    const float scale2 = 2.f * scale;
    const float* sq = &g_sqnorm[bc * NT];

    float snt[8], sns[4];
#pragma unroll
    for (int i = 0; i < 8; ++i) snt[i] = scale * sq[t0 + 8 * ty + i];
#pragma unroll
    for (int j = 0; j < 4; ++j) sns[j] = scale * sq[s0 + 4 * tx + j];

    // arg = -scale*max(nt+ns-2g, 0) = min(scale2*g - (snt+sns), 0)
    float rp[8][4];
#pragma unroll
    for (int i = 0; i < 8; ++i) {
#pragma unroll
        for (int jp = 0; jp < 2; ++jp) {
            float2 g = upk2(acc[i][jp]);
            float a0 = fminf(fmaf(scale2, g.x, -(snt[i] + sns[2 * jp])),     0.f);
            float a1 = fminf(fmaf(scale2, g.y, -(snt[i] + sns[2 * jp + 1])), 0.f);
            rp[i][2 * jp]     = __expf(a0);
            rp[i][2 * jp + 1] = __expf(a1);
        }
    }

    float* ob = out + (size_t)bc * NT * NT;

    // normal tile: rows t, cols s (16B/lane, coalesced across tx)
#pragma unroll
    for (int i = 0; i < 8; ++i) {
        int t = t0 + 8 * ty + i;
        *(float4*)(ob + (size_t)t * NT + s0 + 4 * tx) =
            make_float4(rp[i][0], rp[i][1], rp[i][2], rp[i][3]);
    }

    // transposed tile (skip on diagonal blocks): rows s, cols t.
    // Each lane writes 32B contiguous (full sectors).
    if (ts != ss) {
#pragma unroll
        for (int j = 0; j < 4; ++j) {
            int s = s0 + 4 * tx + j;
            float* dst = ob + (size_t)s * NT + t0 + 8 * ty;
            *(float4*)(dst)     = make_float4(rp[0][j], rp[1][j], rp[2][j], rp[3][j]);
            *(float4*)(dst + 4) = make_float4(rp[4][j], rp[5][j], rp[6][j], rp[7][j]);
        }
    }
}

extern "C" void kernel_launch(void* const* d_in, const int* in_sizes, int n_in,
                              void* d_out, int out_size) {
    const float* x  = (const float*)d_in[0];
    const float* ls = (const float*)d_in[1];
    float* out      = (float*)d_out;

    norms_kernel<<<(NBC * NT + 255) / 256, 256>>>(x, ls);

    dim3 grid(NBC, NPAIR);
    dim3 block(32, 16);
    gaussian_rp_kernel<<<grid, block>>>(x, out);
}

// round 7
// speedup vs baseline: 1.1309x; 1.1309x over previous
#include <cuda_runtime.h>
#include <cstdint>

// GaussianRP: x (8,16,32,1024) f32, log_sigma scalar f32
// out (8,16,1024,1024) f32:
//   rp[b,c,t,s] = exp(-max(|x_t|^2+|x_s|^2-2<x_t,x_s>, 0) / (2 sigma^2))
//
// Round 6: tensor-core Gram via mma.sync.m16n8k8 tf32 with 3xTF32 split
// (x = hi + lo; G = hi*hi + lo*hi + hi*lo, fp32 accumulate -> ~1e-5 error).
// Operands pre-packed in smem in fragment order: A-frags lane-linear LDS.128,
// B-frags lane-linear LDS.64 (conflict-free). 128x128 tile, 512 threads,
// warp = 32x32 sub-tile. Symmetric tile pairs (36/64); transposed stores are
// direct sector-aligned STG.32.

#define NDIM  32
#define NT    1024
#define NBC   128

#define TILE  128
#define NTILE (NT / TILE)                  // 8
#define NPAIR (NTILE * (NTILE + 1) / 2)    // 36

__device__ float g_sqnorm[NBC * NT];
__device__ float g_scale;   // 1/(2 sigma^2)

__global__ __launch_bounds__(256)
void norms_kernel(const float* __restrict__ x,
                  const float* __restrict__ log_sigma) {
    int idx = blockIdx.x * blockDim.x + threadIdx.x;
    if (idx == 0) g_scale = 0.5f * __expf(-2.f * log_sigma[0]);
    if (idx >= NBC * NT) return;
    int bc = idx >> 10;
    int t  = idx & (NT - 1);
    const float* p = x + (size_t)bc * NDIM * NT + t;
    float s = 0.f;
#pragma unroll
    for (int d = 0; d < NDIM; ++d) {
        float v = p[d * NT];
        s = fmaf(v, v, s);
    }
    g_sqnorm[idx] = s;
}

__device__ __forceinline__ uint32_t f2tf32(float v) {
    uint32_t r;
    asm("cvt.rna.tf32.f32 %0, %1;" : "=r"(r) : "f"(v));
    return r;
}

__device__ __forceinline__ void mma_tf32(float d[4],
                                         uint32_t a0, uint32_t a1,
                                         uint32_t a2, uint32_t a3,
                                         uint32_t b0, uint32_t b1) {
    asm volatile(
        "mma.sync.aligned.m16n8k8.row.col.f32.tf32.tf32.f32 "
        "{%0,%1,%2,%3}, {%4,%5,%6,%7}, {%8,%9}, {%0,%1,%2,%3};"
        : "+f"(d[0]), "+f"(d[1]), "+f"(d[2]), "+f"(d[3])
        : "r"(a0), "r"(a1), "r"(a2), "r"(a3), "r"(b0), "r"(b1));
}

// dynamic smem layout (floats): AhiT[4096] AloT[4096] BhiS[4096] BloS[4096]
// A-frag order per (msGlobal 0..7, ks 0..3): 32 lanes x 4 regs [a0,a2,a1,a3]
// B-frag order per (nbGlobal 0..15, ks 0..3): 32 lanes x 2 regs [b0,b1]

__global__ __launch_bounds__(512)
void gaussian_rp_mma(const float* __restrict__ x,
                     float* __restrict__ out) {
    extern __shared__ float sm[];
    float* AhiT = sm;
    float* AloT = sm + 4096;
    float* BhiS = sm + 8192;
    float* BloS = sm + 12288;

    const int bc = blockIdx.x;
    const int p  = blockIdx.y;

    int ss = 0;
#pragma unroll
    for (int c = 1; c < NTILE; ++c)
        ss += (p >= c * (c + 1) / 2) ? 1 : 0;
    const int ts = p - ss * (ss + 1) / 2;
    const int t0 = ts * TILE;
    const int s0 = ss * TILE;

    const int tid  = threadIdx.x;
    const int lane = tid & 31;
    const int wid  = tid >> 5;        // 0..15

    // ---- fill: split x into tf32 hi/lo, packed in fragment order ----
    // thread handles k = lane (one k-row), t-chunk v = wid + 16*r (4 floats).
    const float* xb = x + (size_t)bc * NDIM * NT;
    const int k  = lane;
    const int k3 = k & 3, kb = (k >> 2) & 1, ks = k >> 3;
#pragma unroll
    for (int r = 0; r < 2; ++r) {
        int v = wid + 16 * r;          // 0..31 -> t = 4v..4v+3
        float4 a4 = *(const float4*)(xb + k * NT + t0 + v * 4);
        float4 b4 = *(const float4*)(xb + k * NT + s0 + v * 4);
#pragma unroll
        for (int e = 0; e < 4; ++e) {
            int t = v * 4 + e;         // local 0..127
            // ---- A side (t) ----
            float xa = (&a4.x)[e];
            uint32_t hb = f2tf32(xa);
            float hf = __uint_as_float(hb);
            uint32_t lb = f2tf32(xa - hf);
            int ms   = t >> 4;
            int lA   = ((t & 7) << 2) | k3;
            int idxA = (((t >> 3) & 1) << 1) | kb;   // order [a0,a2,a1,a3]
            int posA = (((ms << 2) | ks) * 32 + lA) * 4 + idxA;
            AhiT[posA] = hf;
            AloT[posA] = __uint_as_float(lb);
            // ---- B side (s) ----
            float xs = (&b4.x)[e];
            uint32_t hb2 = f2tf32(xs);
            float hf2 = __uint_as_float(hb2);
            uint32_t lb2 = f2tf32(xs - hf2);
            int nb   = t >> 3;
            int lB   = ((t & 7) << 2) | k3;
            int idxB = kb;                            // order [b0,b1]
            int posB = (((nb << 2) | ks) * 32 + lB) * 2 + idxB;
            BhiS[posB] = hf2;
            BloS[posB] = __uint_as_float(lb2);
        }
    }
    __syncthreads();

    // ---- warp tiling: warp covers 32(t) x 32(s) ----
    const int wm = wid & 3;            // t-group: rows wm*32..+31
    const int wn = wid >> 2;           // s-group: cols wn*32..+31
    const int g   = lane >> 2;
    const int tig = lane & 3;

    float acc[2][4][4];
#pragma unroll
    for (int i = 0; i < 2; ++i)
#pragma unroll
        for (int j = 0; j < 4; ++j)
#pragma unroll
            for (int q = 0; q < 4; ++q) acc[i][j][q] = 0.f;

    const uint32_t* uAhi = (const uint32_t*)AhiT;
    const uint32_t* uAlo = (const uint32_t*)AloT;
    const uint32_t* uBhi = (const uint32_t*)BhiS;
    const uint32_t* uBlo = (const uint32_t*)BloS;

#pragma unroll
    for (int kk = 0; kk < 4; ++kk) {
        uint4 fh[2], fl[2];
#pragma unroll
        for (int msi = 0; msi < 2; ++msi) {
            int msg = wm * 2 + msi;
            int off = (((msg << 2) | kk) * 32 + lane) * 4;
            fh[msi] = *(const uint4*)(uAhi + off);
            fl[msi] = *(const uint4*)(uAlo + off);
        }
#pragma unroll
        for (int nbl = 0; nbl < 4; ++nbl) {
            int nbg = wn * 4 + nbl;
            int boff = (((nbg << 2) | kk) * 32 + lane) * 2;
            uint2 bh = *(const uint2*)(uBhi + boff);
            uint2 bl = *(const uint2*)(uBlo + boff);
#pragma unroll
            for (int msi = 0; msi < 2; ++msi) {
                // stored order [a0,a2,a1,a3] -> operands (a0,a1,a2,a3)
                mma_tf32(acc[msi][nbl], fh[msi].x, fh[msi].z, fh[msi].y, fh[msi].w, bh.x, bh.y); // hi*hi
                mma_tf32(acc[msi][nbl], fl[msi].x, fl[msi].z, fl[msi].y, fl[msi].w, bh.x, bh.y); // lo*hi
                mma_tf32(acc[msi][nbl], fh[msi].x, fh[msi].z, fh[msi].y, fh[msi].w, bl.x, bl.y); // hi*lo
            }
        }
    }

    // ---- epilogue: d2 -> exp -> dual store ----
    const float scale  = g_scale;
    const float scale2 = 2.f * scale;
    const float* sq = &g_sqnorm[bc * NT];

    float snt[2][2], sns[4][2];
#pragma unroll
    for (int msi = 0; msi < 2; ++msi) {
        int tl = wm * 32 + msi * 16 + g;
        snt[msi][0] = scale * sq[t0 + tl];
        snt[msi][1] = scale * sq[t0 + tl + 8];
    }
#pragma unroll
    for (int nbl = 0; nbl < 4; ++nbl) {
        int sl = wn * 32 + nbl * 8 + 2 * tig;
        sns[nbl][0] = scale * sq[s0 + sl];
        sns[nbl][1] = scale * sq[s0 + sl + 1];
    }

    float* ob = out + (size_t)bc * NT * NT;
    const bool offdiag = (ts != ss);

#pragma unroll
    for (int msi = 0; msi < 2; ++msi) {
#pragma unroll
        for (int nbl = 0; nbl < 4; ++nbl) {
            float* d = acc[msi][nbl];
            // arg = min(2*scale*G - snt - sns, 0); rp = exp(arg)
            float r0 = __expf(fminf(fmaf(scale2, d[0], -(snt[msi][0] + sns[nbl][0])), 0.f));
            float r1 = __expf(fminf(fmaf(scale2, d[1], -(snt[msi][0] + sns[nbl][1])), 0.f));
            float r2 = __expf(fminf(fmaf(scale2, d[2], -(snt[msi][1] + sns[nbl][0])), 0.f));
            float r3 = __expf(fminf(fmaf(scale2, d[3], -(snt[msi][1] + sns[nbl][1])), 0.f));

            int tl = wm * 32 + msi * 16 + g;       // local t (first row)
            int sl = wn * 32 + nbl * 8 + 2 * tig;  // local s (first col)

            // normal tile: rows t, contiguous (s,s+1) pairs -> 32B/quarter-warp
            *(float2*)(ob + (size_t)(t0 + tl) * NT + s0 + sl)     = make_float2(r0, r1);
            *(float2*)(ob + (size_t)(t0 + tl + 8) * NT + s0 + sl) = make_float2(r2, r3);

            // transposed tile: rows s, t runs over g (8 consecutive per quad)
            // -> each STG.32 instruction covers 4 full 32B sectors.
            if (offdiag) {
                ob[(size_t)(s0 + sl)     * NT + t0 + tl]     = r0;
                ob[(size_t)(s0 + sl + 1) * NT + t0 + tl]     = r1;
                ob[(size_t)(s0 + sl)     * NT + t0 + tl + 8] = r2;
                ob[(size_t)(s0 + sl + 1) * NT + t0 + tl + 8] = r3;
            }
        }
    }
}

extern "C" void kernel_launch(void* const* d_in, const int* in_sizes, int n_in,
                              void* d_out, int out_size) {
    const float* x  = (const float*)d_in[0];
    const float* ls = (const float*)d_in[1];
    float* out      = (float*)d_out;

    cudaFuncSetAttribute(gaussian_rp_mma,
                         cudaFuncAttributeMaxDynamicSharedMemorySize, 65536);

    norms_kernel<<<(NBC * NT + 255) / 256, 256>>>(x, ls);

    dim3 grid(NBC, NPAIR);
    gaussian_rp_mma<<<grid, 512, 65536>>>(x, out);
}